// round 16
// baseline (speedup 1.0000x reference)
#include <cuda_runtime.h>
#include <cuda_fp16.h>
#include <cstdint>
#include <cstring>

// BitConv2dInfer via Winograd F(2x2,3x3) + warp-level HMMA fp16:
// y = conv2d(x, ternary_w) * s + bias
// R15 = R14 with the st.global.cs streaming hint REVERTED (V must stay
// L2-resident for the main kernel; .cs evicted it and cost 13 us in main).
// Prep kernel keeps full-sector 256B warp stores + merged wtransform plane.
// Main GEMM kernel frozen at R12 (best known).

#define CIN    128
#define COUT   256
#define HH     56
#define WW     56
#define TILES  28              // 28x28 tiles of 2x2 per image
#define NTILES (32 * TILES * TILES)   // 25088
#define ROWB   272             // smem row stride in main kernel (bank-safe)

// main-kernel smem: 2 x (V 64x272 + U 64x272) + s/bias
#define ABYTES   (64 * ROWB)           // 17408
#define BUFBYTES (2 * ABYTES)          // 34816
#define SS_OFF   (2 * BUFBYTES)        // 69632
#define SB_OFF   (SS_OFF + 256)
#define SMEM_TOTAL (SB_OFF + 256)      // 70144

// prep-kernel smem: x tile [6r][58c][65pad] f32
#define PREP_SMEM (6 * 58 * 65 * 4)    // 90480

#define LDSM4(r, a) \
    asm volatile("ldmatrix.sync.aligned.m8n8.x4.shared.b16 {%0,%1,%2,%3}, [%4];" \
        : "=r"((r)[0]), "=r"((r)[1]), "=r"((r)[2]), "=r"((r)[3]) : "r"(a))

#define MMA16816(c, a, b0, b1) \
    asm volatile("mma.sync.aligned.m16n8k16.row.col.f32.f16.f16.f32 " \
        "{%0,%1,%2,%3}, {%4,%5,%6,%7}, {%8,%9}, {%0,%1,%2,%3};" \
        : "+f"((c)[0]), "+f"((c)[1]), "+f"((c)[2]), "+f"((c)[3]) \
        : "r"((a)[0]), "r"((a)[1]), "r"((a)[2]), "r"((a)[3]), "r"(b0), "r"(b1))

#define CP_ASYNC16(dst, src) \
    asm volatile("cp.async.cg.shared.global [%0], [%1], 16;" \
        :: "r"(dst), "l"(src) : "memory")
#define CP_COMMIT() asm volatile("cp.async.commit_group;" ::: "memory")
#define CP_WAIT(n)  asm volatile("cp.async.wait_group %0;" :: "n"(n) : "memory")

__device__ __forceinline__ uint32_t smem_u32(const void* p) {
    uint32_t a;
    asm("{ .reg .u64 t; cvta.to.shared.u64 t, %1; cvt.u32.u64 %0, t; }" : "=r"(a) : "l"(p));
    return a;
}

// ---------------- scratch ----------------
// U: [xv 16][cog 4][co 64][ci 128] fp16  (1.0 MB, L2-resident)
__device__ __align__(16) __half g_U[16 * 4 * 64 * 128];
// V: [xv 16][gtile 25088][ci 128] fp16   (102.8 MB, mostly L2-resident)
__device__ __align__(16) __half g_V[(size_t)16 * NTILES * 128];

// ---------------- prep kernel: input transform + weight transform ----------
// grid (2 cig, 14 thp, 33): z<32 -> V=Bt d B for image z (64 ci, 2 tile-rows);
// z==32 -> U=G g Gt (28 blocks cover all 32768 (co,ci) pairs).
__global__ void __launch_bounds__(256, 2)
prep_kernel(const float* __restrict__ x, const void* __restrict__ wq) {
    const int t = threadIdx.x;

    if (blockIdx.z == 32) {
        // ===== weight transform (with in-block parallel dtype probe) =====
        const float* wfp = (const float*)wq;
        const int*   wip = (const int*)wq;
        // probe first 256 elements (1024B max: in-bounds under all dtypes;
        // ternary data makes the interpretations mutually exclusive)
        float fv = wfp[t];
        int   iv = wip[t];
        int f32ok = (fv == -1.0f || fv == 0.0f || fv == 1.0f);
        int i32ok = (iv == -1 || iv == 0 || iv == 1);
        int allf = __syncthreads_and(f32ok);
        int alli = __syncthreads_and(i32ok);
        __shared__ int s_wt;
        if (t == 0) s_wt = allf ? 2 : (alli ? 1 : 0);
        __syncthreads();
        const int wt = s_wt;

        const int flat = blockIdx.x * 14 + blockIdx.y;   // 0..27
        for (int e = flat * 256 + t; e < COUT * CIN; e += 28 * 256) {
            int ci = e & 127;
            int co = e >> 7;
            float g[3][3];
            #pragma unroll
            for (int k = 0; k < 9; k++) {
                size_t idx = (size_t)e * 9 + k;
                float v;
                if (wt == 0)      v = (float)((const signed char*)wq)[idx];
                else if (wt == 1) v = (float)wip[idx];
                else              v = wfp[idx];
                g[k / 3][k % 3] = v;
            }
            float T[4][3];
            #pragma unroll
            for (int j = 0; j < 3; j++) {
                T[0][j] = g[0][j];
                T[1][j] = 0.5f * (g[0][j] + g[1][j] + g[2][j]);
                T[2][j] = 0.5f * (g[0][j] - g[1][j] + g[2][j]);
                T[3][j] = g[2][j];
            }
            size_t base = ((size_t)(co >> 6) * 64 + (co & 63)) * 128 + ci;
            #pragma unroll
            for (int i = 0; i < 4; i++) {
                float u0 = T[i][0];
                float u1 = 0.5f * (T[i][0] + T[i][1] + T[i][2]);
                float u2 = 0.5f * (T[i][0] - T[i][1] + T[i][2]);
                float u3 = T[i][2];
                g_U[(size_t)(i * 4 + 0) * (4 * 64 * 128) + base] = __float2half(u0);
                g_U[(size_t)(i * 4 + 1) * (4 * 64 * 128) + base] = __float2half(u1);
                g_U[(size_t)(i * 4 + 2) * (4 * 64 * 128) + base] = __float2half(u2);
                g_U[(size_t)(i * 4 + 3) * (4 * 64 * 128) + base] = __float2half(u3);
            }
        }
        return;
    }

    // ===== input transform: 64 ci x 2 tile-rows x 28 tw =====
    extern __shared__ float sD[];                // [(r*58 + c)*65 + ci]
    const int cig = blockIdx.x;                  // 0..1 (64 ci each)
    const int thp = blockIdx.y;                  // tile-row pair
    const int n   = blockIdx.z;

    // load 6 rows x 58 halo-cols x 64 ci (zero-padded); c fastest -> gmem
    // coalesced; smem stride 65 words -> +1 bank per lane, conflict-free.
    for (int i = t; i < 64 * 6 * 58; i += 256) {
        int c   = i % 58;
        int rem = i / 58;
        int r   = rem % 6;
        int ci  = rem / 6;
        int gh  = 4 * thp - 1 + r;
        int gw  = c - 1;
        float v = 0.0f;
        if ((unsigned)gh < HH && (unsigned)gw < WW)
            v = x[((size_t)(n * CIN + cig * 64 + ci) * HH + gh) * WW + gw];
        sD[(r * 58 + c) * 65 + ci] = v;
    }
    __syncthreads();

    // warp-per-tile: 56 tiles, 8 warps x 7 each; lanes = 32 ci-pairs ->
    // each half2 slab store is 256B contiguous (full sectors). Default
    // write-back stores: V must stay L2-resident for the main kernel.
    const int warp = t >> 5;
    const int lane = t & 31;
    const int ci0  = 2 * lane;
    const size_t sl = (size_t)NTILES * 128;
    for (int tile = warp; tile < 56; tile += 8) {
        int rr = tile / 28;
        int tw = tile - rr * 28;
        float d[2][4][4];
        #pragma unroll
        for (int r = 0; r < 4; r++)
            #pragma unroll
            for (int j = 0; j < 4; j++) {
                int base = ((rr * 2 + r) * 58 + 2 * tw + j) * 65 + ci0;
                d[0][r][j] = sD[base];
                d[1][r][j] = sD[base + 1];
            }
        float tr[2][4][4];
        #pragma unroll
        for (int q = 0; q < 2; q++)
            #pragma unroll
            for (int j = 0; j < 4; j++) {
                tr[q][0][j] = d[q][0][j] - d[q][2][j];
                tr[q][1][j] = d[q][1][j] + d[q][2][j];
                tr[q][2][j] = d[q][2][j] - d[q][1][j];
                tr[q][3][j] = d[q][1][j] - d[q][3][j];
            }
        int th = 2 * thp + rr;
        int gt = (n * TILES + th) * TILES + tw;
        size_t base = (size_t)gt * 128 + cig * 64 + ci0;
        #pragma unroll
        for (int r = 0; r < 4; r++) {
            float v0[2], v1[2], v2[2], v3[2];
            #pragma unroll
            for (int q = 0; q < 2; q++) {
                v0[q] = tr[q][r][0] - tr[q][r][2];
                v1[q] = tr[q][r][1] + tr[q][r][2];
                v2[q] = tr[q][r][2] - tr[q][r][1];
                v3[q] = tr[q][r][1] - tr[q][r][3];
            }
            *(__half2*)&g_V[(size_t)(r * 4 + 0) * sl + base] = __floats2half2_rn(v0[0], v0[1]);
            *(__half2*)&g_V[(size_t)(r * 4 + 1) * sl + base] = __floats2half2_rn(v1[0], v1[1]);
            *(__half2*)&g_V[(size_t)(r * 4 + 2) * sl + base] = __floats2half2_rn(v2[0], v2[1]);
            *(__half2*)&g_V[(size_t)(r * 4 + 3) * sl + base] = __floats2half2_rn(v3[0], v3[1]);
        }
    }
}

// ---------------- main GEMM + fused inverse transform (R12, frozen) --------
__global__ void __launch_bounds__(256, 2)
winograd_main_kernel(const float* __restrict__ s,
                     const float* __restrict__ bias,
                     float* __restrict__ out)
{
    extern __shared__ char smem[];
    const uint32_t smb = smem_u32(smem);
    const int t   = threadIdx.x;
    const int wid = t >> 5;
    const int lid = t & 31;
    const int wm  = wid >> 2;          // 0..1 : 32-tile group
    const int wn  = wid & 3;           // 0..3 : 16-co group

    const int cog = blockIdx.x;        // 0..3  (fastest -> L2 V reuse)
    const int mb  = blockIdx.y;        // 0..391

    if (t < 64) {
        ((float*)(smem + SS_OFF))[t] = s[cog * 64 + t];
        ((float*)(smem + SB_OFF))[t] = bias[cog * 64 + t];
    }

    const uint32_t aoff = (uint32_t)((wm * 32 + (lid & 15)) * ROWB + (lid >> 4) * 16);
    const int b_grp  = lid >> 3;
    const int b_co   = ((b_grp >= 2) ? 8 : 0) + (lid & 7);
    const uint32_t boff = (uint32_t)((wn * 16 + b_co) * ROWB + (b_grp & 1) * 16);

    float y[2][2][4][4];
    #pragma unroll
    for (int a = 0; a < 2; a++)
        #pragma unroll
        for (int b = 0; b < 2; b++)
            #pragma unroll
            for (int e = 0; e < 4; e++)
                #pragma unroll
                for (int q = 0; q < 4; q++) y[a][b][e][q] = 0.0f;

    // stage xv: V + U slabs, 256B gmem rows -> 272B smem rows (row-mapped;
    // the 16B smem pad is never read by ldmatrix)
    auto stage = [&](int xv, int buf) {
        const uint32_t base = smb + buf * BUFBYTES;
        const char* asrc = (const char*)(g_V + ((size_t)xv * NTILES + mb * 64) * 128);
        #pragma unroll
        for (int i = 0; i < 4; i++) {
            int idx = t + i * 256;
            CP_ASYNC16(base + (idx >> 4) * ROWB + (idx & 15) * 16, asrc + idx * 16);
        }
        const char* bsrc = (const char*)(g_U + (size_t)(xv * 4 + cog) * 64 * 128);
        #pragma unroll
        for (int i = 0; i < 4; i++) {
            int idx = t + i * 256;
            CP_ASYNC16(base + ABYTES + (idx >> 4) * ROWB + (idx & 15) * 16, bsrc + idx * 16);
        }
    };

    stage(0, 0); CP_COMMIT();

    #pragma unroll
    for (int xv = 0; xv < 16; xv++) {
        CP_WAIT(0);
        __syncthreads();
        if (xv + 1 < 16) { stage(xv + 1, (xv + 1) & 1); CP_COMMIT(); }

        const uint32_t abase = smb + (xv & 1) * BUFBYTES;
        const uint32_t bbase = abase + ABYTES;

        float c[2][2][4];
        #pragma unroll
        for (int a = 0; a < 2; a++)
            #pragma unroll
            for (int b = 0; b < 2; b++)
                #pragma unroll
                for (int e = 0; e < 4; e++) c[a][b][e] = 0.0f;

        #pragma unroll
        for (int k = 0; k < 8; k++) {
            uint32_t bfr[4];
            LDSM4(bfr, bbase + boff + k * 32);
            #pragma unroll
            for (int mt = 0; mt < 2; mt++) {
                uint32_t afr[4];
                LDSM4(afr, abase + aoff + (uint32_t)(mt * 16 * ROWB) + k * 32);
                MMA16816(c[mt][0], afr, bfr[0], bfr[1]);
                MMA16816(c[mt][1], afr, bfr[2], bfr[3]);
            }
        }

        constexpr float AT0[4] = {1.f, 1.f, 1.f, 0.f};
        constexpr float AT1[4] = {0.f, 1.f, -1.f, -1.f};
        const int xi = xv >> 2, nu = xv & 3;
        const float w00 = AT0[xi] * AT0[nu];
        const float w01 = AT0[xi] * AT1[nu];
        const float w10 = AT1[xi] * AT0[nu];
        const float w11 = AT1[xi] * AT1[nu];
        #pragma unroll
        for (int mt = 0; mt < 2; mt++)
            #pragma unroll
            for (int nt = 0; nt < 2; nt++)
                #pragma unroll
                for (int e = 0; e < 4; e++) {
                    float cv = c[mt][nt][e];
                    if (w00 != 0.f) y[mt][nt][e][0] = fmaf(w00, cv, y[mt][nt][e][0]);
                    if (w01 != 0.f) y[mt][nt][e][1] = fmaf(w01, cv, y[mt][nt][e][1]);
                    if (w10 != 0.f) y[mt][nt][e][2] = fmaf(w10, cv, y[mt][nt][e][2]);
                    if (w11 != 0.f) y[mt][nt][e][3] = fmaf(w11, cv, y[mt][nt][e][3]);
                }
    }

    // ---- epilogue: *s + bias, float2 per 2x2 tile row ----
    {
        const float* ss = (const float*)(smem + SS_OFF);
        const float* sb = (const float*)(smem + SB_OFF);
        const int r0 = lid >> 2;
        const int cq = (lid & 3) * 2;
        #pragma unroll
        for (int mt = 0; mt < 2; mt++)
            #pragma unroll
            for (int half = 0; half < 2; half++) {
                int tl = wm * 32 + mt * 16 + r0 + half * 8;
                int gt = mb * 64 + tl;
                int n  = gt / (TILES * TILES);
                int rm = gt - n * (TILES * TILES);
                int th = rm / TILES;
                int tw = rm - th * TILES;
                #pragma unroll
                for (int nt = 0; nt < 2; nt++)
                    #pragma unroll
                    for (int eo = 0; eo < 2; eo++) {
                        int e   = half * 2 + eo;
                        int col = wn * 16 + nt * 8 + cq + eo;
                        int co  = cog * 64 + col;
                        float sv = ss[col], bv = sb[col];
                        size_t rowbase = (((size_t)n * COUT + co) * HH) * WW;
                        #pragma unroll
                        for (int i = 0; i < 2; i++) {
                            float2 o;
                            o.x = y[mt][nt][e][i * 2 + 0] * sv + bv;
                            o.y = y[mt][nt][e][i * 2 + 1] * sv + bv;
                            *(float2*)&out[rowbase + (size_t)(2 * th + i) * WW + 2 * tw] = o;
                        }
                    }
            }
    }
}

extern "C" void kernel_launch(void* const* d_in, const int* in_sizes, int n_in,
                              void* d_out, int out_size)
{
    const float* xp = (const float*)d_in[0];
    const void*  wp = d_in[1];
    const float* sp = (const float*)d_in[2];
    const float* bp = (const float*)d_in[3];
    float*       op = (float*)d_out;

    cudaFuncSetAttribute(prep_kernel,
                         cudaFuncAttributeMaxDynamicSharedMemorySize, PREP_SMEM);
    cudaFuncSetAttribute(winograd_main_kernel,
                         cudaFuncAttributeMaxDynamicSharedMemorySize, SMEM_TOTAL);

    {
        dim3 pg(2, 14, 33);           // (ci-halves, tile-row pairs, batch + weights plane)
        prep_kernel<<<pg, 256, PREP_SMEM>>>(xp, wp);
    }
    {
        dim3 mg(4, NTILES / 64, 1);   // (co-groups FASTEST, 392 tile-blocks)
        winograd_main_kernel<<<mg, 256, SMEM_TOTAL>>>(sp, bp, op);
    }
}

// round 17
// speedup vs baseline: 1.0920x; 1.0920x over previous
#include <cuda_runtime.h>
#include <cuda_fp16.h>
#include <cstdint>

// BitConv2dInfer via Winograd F(2x2,3x3) + warp-level HMMA fp16:
// y = conv2d(x, ternary_w) * s + bias
// R16: reassembled from measured-best components.
//  - main kernel  = R10 verbatim (measured 130.2 us)
//  - vtransform   = R10 verbatim (2-row halo, occ3, half2 stores)
//  - wtransform   = with in-block parallel dtype probe (kills probe kernel)

#define CIN    128
#define COUT   256
#define HH     56
#define WW     56
#define TILES  28              // 28x28 tiles of 2x2 per image
#define NTILES (32 * TILES * TILES)   // 25088
#define CIPAD  136             // 128 ci + 8 pad halves -> 272B rows (bank-safe)
#define ROWB   272

// main-kernel smem: 2 x (V 64x272 + U 64x272) + s/bias
#define ABYTES   (64 * ROWB)           // 17408
#define BUFBYTES (2 * ABYTES)          // 34816
#define SS_OFF   (2 * BUFBYTES)        // 69632
#define SB_OFF   (SS_OFF + 256)
#define SMEM_TOTAL (SB_OFF + 256)      // 70144

#define LDSM4(r, a) \
    asm volatile("ldmatrix.sync.aligned.m8n8.x4.shared.b16 {%0,%1,%2,%3}, [%4];" \
        : "=r"((r)[0]), "=r"((r)[1]), "=r"((r)[2]), "=r"((r)[3]) : "r"(a))

#define MMA16816(c, a, b0, b1) \
    asm volatile("mma.sync.aligned.m16n8k16.row.col.f32.f16.f16.f32 " \
        "{%0,%1,%2,%3}, {%4,%5,%6,%7}, {%8,%9}, {%0,%1,%2,%3};" \
        : "+f"((c)[0]), "+f"((c)[1]), "+f"((c)[2]), "+f"((c)[3]) \
        : "r"((a)[0]), "r"((a)[1]), "r"((a)[2]), "r"((a)[3]), "r"(b0), "r"(b1))

#define CP_ASYNC16(dst, src) \
    asm volatile("cp.async.cg.shared.global [%0], [%1], 16;" \
        :: "r"(dst), "l"(src) : "memory")
#define CP_COMMIT() asm volatile("cp.async.commit_group;" ::: "memory")
#define CP_WAIT(n)  asm volatile("cp.async.wait_group %0;" :: "n"(n) : "memory")

__device__ __forceinline__ uint32_t smem_u32(const void* p) {
    uint32_t a;
    asm("{ .reg .u64 t; cvta.to.shared.u64 t, %1; cvt.u32.u64 %0, t; }" : "=r"(a) : "l"(p));
    return a;
}

// ---------------- scratch ----------------
// U: [xv 16][cog 4][co 64][ci 136pad] fp16  (1.1 MB, L2-resident)
__device__ __align__(16) __half g_U[16 * 4 * 64 * CIPAD];
// V: [xv 16][gtile 25088][ci 136pad] fp16   (109 MB)
__device__ __align__(16) __half g_V[(size_t)16 * NTILES * CIPAD];

// ---------------- weight transform: U = G g Gt (in-block dtype probe) ------
__global__ void wtransform_kernel(const void* __restrict__ wq) {
    const float* wfp = (const float*)wq;
    const int*   wip = (const int*)wq;
    // Parallel dtype probe on the first 256 elements (1024B max: in-bounds
    // under every candidate dtype; ternary data makes the interpretations
    // mutually exclusive). Every block derives the same answer.
    int tt = threadIdx.x;
    float fv = wfp[tt];
    int   iv = wip[tt];
    int f32ok = (fv == -1.0f || fv == 0.0f || fv == 1.0f);
    int i32ok = (iv == -1 || iv == 0 || iv == 1);
    int allf = __syncthreads_and(f32ok);
    int alli = __syncthreads_and(i32ok);
    __shared__ int s_wt;
    if (threadIdx.x == 0) s_wt = allf ? 2 : (alli ? 1 : 0);
    __syncthreads();
    const int wt = s_wt;

    int e = blockIdx.x * 256 + threadIdx.x;     // e = co*CIN + ci
    if (e >= COUT * CIN) return;
    int ci = e & 127;
    int co = e >> 7;
    float g[3][3];
    #pragma unroll
    for (int k = 0; k < 9; k++) {
        size_t idx = (size_t)e * 9 + k;
        float v;
        if (wt == 0)      v = (float)((const signed char*)wq)[idx];
        else if (wt == 1) v = (float)wip[idx];
        else              v = wfp[idx];
        g[k / 3][k % 3] = v;
    }
    float T[4][3];
    #pragma unroll
    for (int j = 0; j < 3; j++) {
        T[0][j] = g[0][j];
        T[1][j] = 0.5f * (g[0][j] + g[1][j] + g[2][j]);
        T[2][j] = 0.5f * (g[0][j] - g[1][j] + g[2][j]);
        T[3][j] = g[2][j];
    }
    size_t base = ((size_t)(co >> 6) * 64 + (co & 63)) * CIPAD + ci;
    #pragma unroll
    for (int i = 0; i < 4; i++) {
        float u0 = T[i][0];
        float u1 = 0.5f * (T[i][0] + T[i][1] + T[i][2]);
        float u2 = 0.5f * (T[i][0] - T[i][1] + T[i][2]);
        float u3 = T[i][2];
        g_U[(size_t)(i * 4 + 0) * (4 * 64 * CIPAD) + base] = __float2half(u0);
        g_U[(size_t)(i * 4 + 1) * (4 * 64 * CIPAD) + base] = __float2half(u1);
        g_U[(size_t)(i * 4 + 2) * (4 * 64 * CIPAD) + base] = __float2half(u2);
        g_U[(size_t)(i * 4 + 3) * (4 * 64 * CIPAD) + base] = __float2half(u3);
    }
}

// ---------------- input transform: V = Bt d B (R10 verbatim) ----------------
// block = (cig 4, thp 14, n 32): 32 ci x 2 tile-rows x 28 tw (6-row halo).
__global__ void __launch_bounds__(256, 3)
vtransform_kernel(const float* __restrict__ x) {
    __shared__ float sD[6 * 32 * 61];           // [r][ci][c 58used/61pad]
    const int cig = blockIdx.x;
    const int thp = blockIdx.y;                 // tile-row pair
    const int n   = blockIdx.z;
    const int t   = threadIdx.x;

    for (int i = t; i < 6 * 32 * 58; i += 256) {
        int c   = i % 58;
        int rem = i / 58;
        int ci  = rem & 31;
        int r   = rem >> 5;
        int gh  = 4 * thp - 1 + r;
        int gw  = c - 1;
        float v = 0.0f;
        if ((unsigned)gh < HH && (unsigned)gw < WW)
            v = x[((size_t)(n * CIN + cig * 32 + ci) * HH + gh) * WW + gw];
        sD[(r * 32 + ci) * 61 + c] = v;
    }
    __syncthreads();

    // items = (ci pair 16) x (tw 28) x (row-in-pair 2)
    for (int i = t; i < 16 * 28 * 2; i += 256) {
        int cp  = i & 15;
        int rem = i >> 4;
        int tw  = rem % 28;
        int rr  = rem / 28;
        int ci0 = 2 * cp;
        float d[2][4][4];
        #pragma unroll
        for (int q = 0; q < 2; q++)
            #pragma unroll
            for (int r = 0; r < 4; r++)
                #pragma unroll
                for (int j = 0; j < 4; j++)
                    d[q][r][j] = sD[((rr * 2 + r) * 32 + ci0 + q) * 61 + 2 * tw + j];
        float tr[2][4][4];
        #pragma unroll
        for (int q = 0; q < 2; q++)
            #pragma unroll
            for (int j = 0; j < 4; j++) {
                tr[q][0][j] = d[q][0][j] - d[q][2][j];
                tr[q][1][j] = d[q][1][j] + d[q][2][j];
                tr[q][2][j] = d[q][2][j] - d[q][1][j];
                tr[q][3][j] = d[q][1][j] - d[q][3][j];
            }
        int th = 2 * thp + rr;
        int gt = (n * TILES + th) * TILES + tw;
        size_t base = (size_t)gt * CIPAD + cig * 32 + ci0;
        size_t sl   = (size_t)NTILES * CIPAD;
        #pragma unroll
        for (int r = 0; r < 4; r++) {
            float v0[2], v1[2], v2[2], v3[2];
            #pragma unroll
            for (int q = 0; q < 2; q++) {
                v0[q] = tr[q][r][0] - tr[q][r][2];
                v1[q] = tr[q][r][1] + tr[q][r][2];
                v2[q] = tr[q][r][2] - tr[q][r][1];
                v3[q] = tr[q][r][1] - tr[q][r][3];
            }
            *(__half2*)&g_V[(size_t)(r * 4 + 0) * sl + base] = __floats2half2_rn(v0[0], v0[1]);
            *(__half2*)&g_V[(size_t)(r * 4 + 1) * sl + base] = __floats2half2_rn(v1[0], v1[1]);
            *(__half2*)&g_V[(size_t)(r * 4 + 2) * sl + base] = __floats2half2_rn(v2[0], v2[1]);
            *(__half2*)&g_V[(size_t)(r * 4 + 3) * sl + base] = __floats2half2_rn(v3[0], v3[1]);
        }
    }
}

// ---------------- main GEMM + fused inverse transform (R10 verbatim) -------
// grid (4 cog FASTEST, 392 mblocks); CTA: 64 tiles x 64 co, 256 threads,
// 2 CTA/SM; warps 2m x 4n; 2-stage pipeline, one barrier per xv; xv loop
// fully unrolled with compile-time AT fold weights; FLAT contiguous staging
// (272B gmem rows == smem rows).
__global__ void __launch_bounds__(256, 2)
winograd_main_kernel(const float* __restrict__ s,
                     const float* __restrict__ bias,
                     float* __restrict__ out)
{
    extern __shared__ char smem[];
    const uint32_t smb = smem_u32(smem);
    const int t   = threadIdx.x;
    const int wid = t >> 5;
    const int lid = t & 31;
    const int wm  = wid >> 2;          // 0..1 : 32-tile group
    const int wn  = wid & 3;           // 0..3 : 16-co group

    const int cog = blockIdx.x;        // 0..3  (fastest -> L2 V reuse)
    const int mb  = blockIdx.y;        // 0..391

    if (t < 64) {
        ((float*)(smem + SS_OFF))[t] = s[cog * 64 + t];
        ((float*)(smem + SB_OFF))[t] = bias[cog * 64 + t];
    }

    // per-lane ldmatrix offsets (272B row stride -> conflict-free)
    const uint32_t aoff = (uint32_t)((wm * 32 + (lid & 15)) * ROWB + (lid >> 4) * 16);
    const int b_grp  = lid >> 3;
    const int b_co   = ((b_grp >= 2) ? 8 : 0) + (lid & 7);
    const uint32_t boff = (uint32_t)((wn * 16 + b_co) * ROWB + (b_grp & 1) * 16);

    float y[2][2][4][4];               // [mt][nt][frag elem][i*2+j]
    #pragma unroll
    for (int a = 0; a < 2; a++)
        #pragma unroll
        for (int b = 0; b < 2; b++)
            #pragma unroll
            for (int e = 0; e < 4; e++)
                #pragma unroll
                for (int q = 0; q < 4; q++) y[a][b][e][q] = 0.0f;

    // stage xv into buf: V 17408B + U 17408B flat copies (pre-padded slabs)
    auto stage = [&](int xv, int buf) {
        const uint32_t base = smb + buf * BUFBYTES;
        const char* asrc = (const char*)g_V + ((size_t)xv * NTILES + mb * 64) * ROWB;
        #pragma unroll
        for (int i = 0; i < 5; i++) {
            int idx = t + i * 256;
            if (idx < ABYTES / 16) CP_ASYNC16(base + idx * 16, asrc + idx * 16);
        }
        const char* bsrc = (const char*)g_U + (size_t)(xv * 4 + cog) * 64 * ROWB;
        #pragma unroll
        for (int i = 0; i < 5; i++) {
            int idx = t + i * 256;
            if (idx < ABYTES / 16) CP_ASYNC16(base + ABYTES + idx * 16, bsrc + idx * 16);
        }
    };

    stage(0, 0);
    CP_COMMIT();

    #pragma unroll
    for (int xv = 0; xv < 16; xv++) {
        CP_WAIT(0);                    // copies for buf[xv&1] complete
        __syncthreads();               // visible to all; all warps done xv-1
        if (xv + 1 < 16) { stage(xv + 1, (xv + 1) & 1); CP_COMMIT(); }

        const uint32_t abase = smb + (xv & 1) * BUFBYTES;
        const uint32_t bbase = abase + ABYTES;

        float c[2][2][4];
        #pragma unroll
        for (int a = 0; a < 2; a++)
            #pragma unroll
            for (int b = 0; b < 2; b++)
                #pragma unroll
                for (int e = 0; e < 4; e++) c[a][b][e] = 0.0f;

        #pragma unroll
        for (int k = 0; k < 8; k++) {
            uint32_t bfr[4];
            LDSM4(bfr, bbase + boff + k * 32);
            #pragma unroll
            for (int mt = 0; mt < 2; mt++) {
                uint32_t afr[4];
                LDSM4(afr, abase + aoff + (uint32_t)(mt * 16 * ROWB) + k * 32);
                MMA16816(c[mt][0], afr, bfr[0], bfr[1]);
                MMA16816(c[mt][1], afr, bfr[2], bfr[3]);
            }
        }

        // fold C into y with COMPILE-TIME At coefficients (xv unrolled)
        constexpr float AT0[4] = {1.f, 1.f, 1.f, 0.f};
        constexpr float AT1[4] = {0.f, 1.f, -1.f, -1.f};
        const int xi = xv >> 2, nu = xv & 3;
        const float w00 = AT0[xi] * AT0[nu];
        const float w01 = AT0[xi] * AT1[nu];
        const float w10 = AT1[xi] * AT0[nu];
        const float w11 = AT1[xi] * AT1[nu];
        #pragma unroll
        for (int mt = 0; mt < 2; mt++)
            #pragma unroll
            for (int nt = 0; nt < 2; nt++)
                #pragma unroll
                for (int e = 0; e < 4; e++) {
                    float cv = c[mt][nt][e];
                    if (w00 != 0.f) y[mt][nt][e][0] = fmaf(w00, cv, y[mt][nt][e][0]);
                    if (w01 != 0.f) y[mt][nt][e][1] = fmaf(w01, cv, y[mt][nt][e][1]);
                    if (w10 != 0.f) y[mt][nt][e][2] = fmaf(w10, cv, y[mt][nt][e][2]);
                    if (w11 != 0.f) y[mt][nt][e][3] = fmaf(w11, cv, y[mt][nt][e][3]);
                }
    }

    // ---- epilogue: *s + bias, float2 per 2x2 tile row ----
    {
        const float* ss = (const float*)(smem + SS_OFF);
        const float* sb = (const float*)(smem + SB_OFF);
        const int r0 = lid >> 2;
        const int cq = (lid & 3) * 2;
        #pragma unroll
        for (int mt = 0; mt < 2; mt++)
            #pragma unroll
            for (int half = 0; half < 2; half++) {
                int tl = wm * 32 + mt * 16 + r0 + half * 8;
                int gt = mb * 64 + tl;
                int n  = gt / (TILES * TILES);
                int rm = gt - n * (TILES * TILES);
                int th = rm / TILES;
                int tw = rm - th * TILES;
                #pragma unroll
                for (int nt = 0; nt < 2; nt++)
                    #pragma unroll
                    for (int eo = 0; eo < 2; eo++) {
                        int e   = half * 2 + eo;
                        int col = wn * 16 + nt * 8 + cq + eo;
                        int co  = cog * 64 + col;
                        float sv = ss[col], bv = sb[col];
                        size_t rowbase = (((size_t)n * COUT + co) * HH) * WW;
                        #pragma unroll
                        for (int i = 0; i < 2; i++) {
                            float2 o;
                            o.x = y[mt][nt][e][i * 2 + 0] * sv + bv;
                            o.y = y[mt][nt][e][i * 2 + 1] * sv + bv;
                            *(float2*)&out[rowbase + (size_t)(2 * th + i) * WW + 2 * tw] = o;
                        }
                    }
            }
    }
}

extern "C" void kernel_launch(void* const* d_in, const int* in_sizes, int n_in,
                              void* d_out, int out_size)
{
    const float* xp = (const float*)d_in[0];
    const void*  wp = d_in[1];
    const float* sp = (const float*)d_in[2];
    const float* bp = (const float*)d_in[3];
    float*       op = (float*)d_out;

    cudaFuncSetAttribute(winograd_main_kernel,
                         cudaFuncAttributeMaxDynamicSharedMemorySize, SMEM_TOTAL);

    wtransform_kernel<<<(COUT * CIN + 255) / 256, 256>>>(wp);
    {
        dim3 vg(4, TILES / 2, 32);    // (ci-groups, tile-row pairs, batch)
        vtransform_kernel<<<vg, 256>>>(xp);
    }
    {
        dim3 mg(4, NTILES / 64, 1);   // (co-groups FASTEST, 392 tile-blocks)
        winograd_main_kernel<<<mg, 256, SMEM_TOTAL>>>(sp, bp, op);
    }
}